// round 17
// baseline (speedup 1.0000x reference)
#include <cuda_runtime.h>
#include <cuda_fp16.h>
#include <cuda_bf16.h>
#include <stdint.h>
#include <math.h>

#define NTYPES 10000
#define NG     2000
#define NB     1024

// ---------------- scratch (device globals) ----------------
__device__ __half g_IWh[NTYPES * 128];   // impact @ W.T  (fp16)
__device__ __half g_IMh[NTYPES * 128];   // impact @ M.T  (fp16)
__device__ __half g_W1h[128 * 256];      // W1 in fp16
__device__ float  g_E [NG * 128];        // softmax(per_graph)
__device__ float  g_X [NG * 128];        // softmax(relu(ext))

typedef unsigned long long u64t;
__device__ __forceinline__ u64t pk2(float lo, float hi) {
    u64t r;
    asm("mov.b64 %0, {%1, %2};" : "=l"(r) : "r"(__float_as_uint(lo)), "r"(__float_as_uint(hi)));
    return r;
}
__device__ __forceinline__ float2 upk2(u64t v) {
    unsigned lo, hi;
    asm("mov.b64 {%0, %1}, %2;" : "=r"(lo), "=r"(hi) : "l"(v));
    return make_float2(__uint_as_float(lo), __uint_as_float(hi));
}
#define FMA2(d, a, b) asm("fma.rn.f32x2 %0, %1, %2, %0;" : "+l"(d) : "l"(a), "l"(b))

__device__ __forceinline__ void cpa16(unsigned daddr, const void* src) {
    asm volatile("cp.async.cg.shared.global [%0], [%1], 16;" :: "r"(daddr), "l"(src));
}
__device__ __forceinline__ unsigned smem_u32(const void* p) {
    unsigned a;
    asm("{ .reg .u64 t; cvta.to.shared.u64 t, %1; cvt.u32.u64 %0, t; }" : "=r"(a) : "l"(p));
    return a;
}

// ---------------- mma.sync (sm_80+, legal on base sm_103 target) ------------
__device__ __forceinline__ void ldsm_x4(unsigned& r0, unsigned& r1,
                                        unsigned& r2, unsigned& r3, unsigned addr) {
    asm volatile("ldmatrix.sync.aligned.m8n8.x4.shared.b16 {%0,%1,%2,%3}, [%4];"
                 : "=r"(r0), "=r"(r1), "=r"(r2), "=r"(r3) : "r"(addr));
}
__device__ __forceinline__ void ldsm_x2t(unsigned& r0, unsigned& r1, unsigned addr) {
    asm volatile("ldmatrix.sync.aligned.m8n8.x2.trans.shared.b16 {%0,%1}, [%2];"
                 : "=r"(r0), "=r"(r1) : "r"(addr));
}
__device__ __forceinline__ void mma16816(float* d, const unsigned* a,
                                         unsigned b0, unsigned b1) {
    asm volatile(
        "mma.sync.aligned.m16n8k16.row.col.f32.bf16.bf16.f32 "
        "{%0,%1,%2,%3}, {%4,%5,%6,%7}, {%8,%9}, {%0,%1,%2,%3};"
        : "+f"(d[0]), "+f"(d[1]), "+f"(d[2]), "+f"(d[3])
        : "r"(a[0]), "r"(a[1]), "r"(a[2]), "r"(a[3]), "r"(b0), "r"(b1));
}

// ---- dummy no-op kernel: keeps ncu's -s window on kC ----
__global__ void kNop() {}

// ============================================================================
// Kernel A (HMMA): IW/IM = impact @ {W,M}.T -> fp16 tables.   (unchanged)
// ============================================================================
#define KA_STR 136
#define SMEM_A (3 * 128 * KA_STR * 2 + 16)

__global__ void __launch_bounds__(256) kA(const float* __restrict__ impact,
                                          const float* __restrict__ W,
                                          const float* __restrict__ M,
                                          const float* __restrict__ W1) {
    extern __shared__ __half smh[];
    __half* sA = smh;                    // [128][KA_STR]
    __half* sW = smh + 128 * KA_STR;
    __half* sM = sW + 128 * KA_STR;

    const int tid = threadIdx.x;
    const int warp = tid >> 5, lane = tid & 31;
    const int rowBase = blockIdx.x * 128;

    if (blockIdx.x < 16) {
        const int base = blockIdx.x * 2048;
        for (int q = tid; q < 1024; q += 256) {
            const float2 v = *(const float2*)(W1 + base + (q << 1));
            *(__half2*)(g_W1h + base + (q << 1)) = __floats2half2_rn(v.x, v.y);
        }
    }

    for (int idx = tid; idx < 128 * 64; idx += 256) {
        const int r = idx >> 6, cp = (idx & 63) << 1;
        const int grow = rowBase + r;
        const float2 av = (grow < NTYPES) ? *(const float2*)(impact + (size_t)grow * 128 + cp)
                                          : make_float2(0.f, 0.f);
        const float2 wv = *(const float2*)(W + r * 128 + cp);
        const float2 mv = *(const float2*)(M + r * 128 + cp);
        *(__nv_bfloat162*)(sA + r * KA_STR + cp) = __floats2bfloat162_rn(av.x, av.y);
        *(__nv_bfloat162*)(sW + r * KA_STR + cp) = __floats2bfloat162_rn(wv.x, wv.y);
        *(__nv_bfloat162*)(sM + r * KA_STR + cp) = __floats2bfloat162_rn(mv.x, mv.y);
    }
    __syncthreads();

    const unsigned sbase = smem_u32(smh);
    const int wrb = warp << 4;

    const int aRow = wrb + (lane & 15);
    const unsigned aBase = sbase + ((unsigned)(aRow * KA_STR + ((lane >> 4) << 3)) << 1);
    unsigned a[8][4];
#pragma unroll
    for (int k = 0; k < 8; ++k)
        ldsm_x4(a[k][0], a[k][1], a[k][2], a[k][3], aBase + (k << 5));

    const unsigned bOff = ((unsigned)((lane & 7) * KA_STR + (((lane >> 3) & 1) << 3)) << 1);
    const unsigned wB = sbase + 128 * KA_STR * 2 + bOff;
    const unsigned mB = sbase + 2 * 128 * KA_STR * 2 + bOff;

    const int r0g = rowBase + wrb + (lane >> 2);
    const int r1g = r0g + 8;
    const int cbase = (lane & 3) << 1;

#pragma unroll
    for (int t = 0; t < 2; ++t) {
        const unsigned bb = t ? mB : wB;
        __half* dst = t ? g_IMh : g_IWh;
        float acc[16][4];
#pragma unroll
        for (int n = 0; n < 16; ++n) {
            acc[n][0] = acc[n][1] = acc[n][2] = acc[n][3] = 0.f;
        }
#pragma unroll
        for (int n = 0; n < 16; ++n) {
            const unsigned bn = bb + (unsigned)(n * 8 * KA_STR * 2);
#pragma unroll
            for (int k = 0; k < 8; ++k) {
                unsigned b0, b1;
                ldsm_x2t(b0, b1, bn + (k << 5));
                mma16816(acc[n], a[k], b0, b1);
            }
        }
#pragma unroll
        for (int n = 0; n < 16; ++n) {
            const __half2 h0 = __floats2half2_rn(acc[n][0], acc[n][1]);
            const __half2 h1 = __floats2half2_rn(acc[n][2], acc[n][3]);
            const int col = (n << 3) + cbase;
            if (r0g < NTYPES) *(__half2*)(dst + (size_t)r0g * 128 + col) = h0;
            if (r1g < NTYPES) *(__half2*)(dst + (size_t)r1g * 128 + col) = h1;
        }
    }
}

// ============================================================================
// Kernel B: per_graph gather-sum + softmax -> E.  (unchanged)
// ============================================================================
__global__ void __launch_bounds__(256) kB(const int* __restrict__ node_type,
                                          const int* __restrict__ nbr_type) {
    __shared__ int   sNT[64];
    __shared__ int   sNB[512];
    __shared__ float sP[8][132];
    __shared__ float sredm[8];
    __shared__ float sreds[8];

    const int tid = threadIdx.x;
    const int g = blockIdx.x;
    const int w = tid >> 5, lane = tid & 31;

    if (tid < 64) sNT[tid] = node_type[g * 64 + tid];
    for (int idx = tid; idx < 512; idx += 256) sNB[idx] = nbr_type[g * 512 + idx];
    __syncthreads();

    const int co = lane << 2;   // 4 halves per lane
    float4 acc = make_float4(0.f, 0.f, 0.f, 0.f);
#pragma unroll 2
    for (int kk = 0; kk < 8; ++kk) {
        const int k = (kk << 3) + w;
        const uint2 u = *(const uint2*)(g_IWh + (size_t)sNT[k] * 128 + co);
        __half2 s01 = *(__half2*)&u.x;
        __half2 s23 = *(__half2*)&u.y;
        const int* nbp = &sNB[k << 3];
#pragma unroll
        for (int d = 0; d < 8; ++d) {
            const uint2 v = *(const uint2*)(g_IMh + (size_t)nbp[d] * 128 + co);
            s01 = __hadd2(s01, *(__half2*)&v.x);
            s23 = __hadd2(s23, *(__half2*)&v.y);
        }
        const float2 f01 = __half22float2(s01);
        const float2 f23 = __half22float2(s23);
        acc.x += fmaxf(f01.x, 0.f);
        acc.y += fmaxf(f01.y, 0.f);
        acc.z += fmaxf(f23.x, 0.f);
        acc.w += fmaxf(f23.y, 0.f);
    }
    *(float4*)(&sP[w][co]) = acc;
    __syncthreads();

    float v = 0.f;
    if (tid < 128) {
#pragma unroll
        for (int ww = 0; ww < 8; ++ww) v += sP[ww][tid];
    }
    float m = v;
#pragma unroll
    for (int off = 16; off; off >>= 1)
        m = fmaxf(m, __shfl_xor_sync(0xffffffffu, m, off));
    if (lane == 0) sredm[w] = m;
    __syncthreads();
    const float M = fmaxf(fmaxf(sredm[0], sredm[1]), fmaxf(sredm[2], sredm[3]));

    const float e = (tid < 128) ? expf(v - M) : 0.f;
    float s = e;
#pragma unroll
    for (int off = 16; off; off >>= 1)
        s += __shfl_xor_sync(0xffffffffu, s, off);
    if (lane == 0) sreds[w] = s;
    __syncthreads();
    const float tot = sreds[0] + sreds[1] + sreds[2] + sreds[3];

    if (tid < 128) g_E[g * 128 + tid] = e / tot;
}

// ============================================================================
// Kernel C: ext = E @ U.T + Esum @ V.T ;  X = softmax(relu(ext))
// ONE WAVE: 125 blocks x 16 rows; 512 threads (warp = row); single sync.
// ============================================================================
#define C_WSTR 132
#define C_ASTR 18
#define C_ROWS 16
#define SMEM_C ((2 * 128 * C_WSTR + 2 * 128 * C_ASTR) * 4)

__global__ void __launch_bounds__(512) kC(const float* __restrict__ U,
                                          const float* __restrict__ V,
                                          const int* __restrict__ ext_nbr) {
    extern __shared__ float sm[];
    float* sUt = sm;                       // [128][C_WSTR]  Ut[i][j] = U[j][i]
    float* sVt = sUt + 128 * C_WSTR;
    float* sEt = sVt + 128 * C_WSTR;       // [128][C_ASTR]  E^T tile
    float* sSt = sEt + 128 * C_ASTR;       // [128][C_ASTR]  Esum^T tile

    const int tid = threadIdx.x;
    const int rowBase = blockIdx.x * C_ROWS;   // 125*16 = 2000 exact
    const int r = tid >> 5;                // warp id = local row
    const int tx = tid & 31;               // col group

    // U/V transposed fill (float4 reads, conflict-free scalar scatter)
    for (int idx = tid; idx < 128 * 32; idx += 512) {
        const int j = idx >> 5, i4 = (idx & 31) << 2;
        const float4 u = *(const float4*)(U + j * 128 + i4);
        const float4 v = *(const float4*)(V + j * 128 + i4);
        sUt[(i4 + 0) * C_WSTR + j] = u.x;
        sUt[(i4 + 1) * C_WSTR + j] = u.y;
        sUt[(i4 + 2) * C_WSTR + j] = u.z;
        sUt[(i4 + 3) * C_WSTR + j] = u.w;
        sVt[(i4 + 0) * C_WSTR + j] = v.x;
        sVt[(i4 + 1) * C_WSTR + j] = v.y;
        sVt[(i4 + 2) * C_WSTR + j] = v.z;
        sVt[(i4 + 3) * C_WSTR + j] = v.w;
    }
    // E^T fill: exactly one float4 per thread
    {
        const int c4 = tx << 2;
        const float4 e = *(const float4*)(g_E + (size_t)(rowBase + r) * 128 + c4);
        sEt[(c4 + 0) * C_ASTR + r] = e.x;
        sEt[(c4 + 1) * C_ASTR + r] = e.y;
        sEt[(c4 + 2) * C_ASTR + r] = e.z;
        sEt[(c4 + 3) * C_ASTR + r] = e.w;
    }
    // Esum^T: indices straight from gmem (warp-uniform), one float4 per thread
    {
        const int c4 = tx << 2;
        const int* xn = ext_nbr + (rowBase + r) * 16;
        float4 s = make_float4(0.f, 0.f, 0.f, 0.f);
#pragma unroll
        for (int d = 0; d < 16; ++d) {
            const float4 v = *(const float4*)(g_E + (size_t)__ldg(xn + d) * 128 + c4);
            s.x += v.x; s.y += v.y; s.z += v.z; s.w += v.w;
        }
        sSt[(c4 + 0) * C_ASTR + r] = s.x;
        sSt[(c4 + 1) * C_ASTR + r] = s.y;
        sSt[(c4 + 2) * C_ASTR + r] = s.z;
        sSt[(c4 + 3) * C_ASTR + r] = s.w;
    }
    __syncthreads();

    // GEMM: warp = row, lane = 4 cols
    u64t acc0 = 0, acc1 = 0;
#pragma unroll 4
    for (int i = 0; i < 128; ++i) {
        const float ev = sEt[i * C_ASTR + r];    // warp broadcast
        const float qv = sSt[i * C_ASTR + r];
        const float4 uv = *(const float4*)(sUt + i * C_WSTR + (tx << 2));
        const float4 vv = *(const float4*)(sVt + i * C_WSTR + (tx << 2));
        const u64t u0 = ((const u64t*)&uv)[0], u1 = ((const u64t*)&uv)[1];
        const u64t v0 = ((const u64t*)&vv)[0], v1 = ((const u64t*)&vv)[1];
        const u64t e2 = pk2(ev, ev);
        const u64t s2 = pk2(qv, qv);
        FMA2(acc0, e2, u0); FMA2(acc1, e2, u1);
        FMA2(acc0, s2, v0); FMA2(acc1, s2, v1);
    }

    // relu + softmax over the warp's row
    {
        const int row = rowBase + r;
        const float2 c01 = upk2(acc0);
        const float2 c23 = upk2(acc1);
        float v0 = fmaxf(c01.x, 0.f), v1 = fmaxf(c01.y, 0.f);
        float v2 = fmaxf(c23.x, 0.f), v3 = fmaxf(c23.y, 0.f);
        float m = fmaxf(fmaxf(v0, v1), fmaxf(v2, v3));
#pragma unroll
        for (int off = 16; off; off >>= 1)
            m = fmaxf(m, __shfl_xor_sync(0xffffffffu, m, off));
        float e0 = expf(v0 - m), e1 = expf(v1 - m), e2 = expf(v2 - m), e3 = expf(v3 - m);
        float s = e0 + e1 + e2 + e3;
#pragma unroll
        for (int off = 16; off; off >>= 1)
            s += __shfl_xor_sync(0xffffffffu, s, off);
        const float inv = 1.f / s;
        float4 o = make_float4(e0 * inv, e1 * inv, e2 * inv, e3 * inv);
        *(float4*)(g_X + (size_t)row * 128 + (tx << 2)) = o;
    }
}

// ============================================================================
// Kernel D: ONE WAVE. 128 blocks x 8 rows; 512 threads; cp.async fill. (unchanged)
// ============================================================================
#define D2_STR 264
#define SMEM_D (128 * D2_STR * 2)

__global__ void __launch_bounds__(512) kD(const int* __restrict__ batch,
                                          const float* __restrict__ b1,
                                          const float* __restrict__ W2,
                                          const float* __restrict__ b2,
                                          float* __restrict__ out) {
    extern __shared__ __half sWh[];      // [128][D2_STR]
    __shared__ float sF[8][260];
    __shared__ float sW2[256];
    __shared__ float sB1[128];
    __shared__ float sP[16][2][2];

    const int tid = threadIdx.x;
    const int rg = tid >> 7;
    const int j = tid & 127;
    const int warp = tid >> 5, lane = tid & 31;

    const unsigned sbase = (unsigned)__cvta_generic_to_shared(sWh);
    for (int q = tid; q < 128 * 32; q += 512) {
        const int jr = q >> 5, i8 = (q & 31) << 3;
        cpa16(sbase + (jr * D2_STR + i8) * 2, g_W1h + (q << 3));
    }
    asm volatile("cp.async.commit_group;" ::: "memory");

    if (tid < 256) sW2[tid] = W2[tid];
    if (tid < 128) sB1[tid] = b1[tid];
    const float bb0 = b2[0], bb1 = b2[1];

    const int rb = rg << 1;
#pragma unroll
    for (int rr = 0; rr < 2; ++rr) {
        const int row = blockIdx.x * 8 + rb + rr;
        const int b0i = batch[2 * row];
        const int b1i = batch[2 * row + 1];
        const float e1 = g_X[b0i * 128 + j];
        const float e2 = g_X[b1i * 128 + j];
        sF[rb + rr][j] = e1 * e2;
        sF[rb + rr][128 + j] = e1 + e2;
    }
    asm volatile("cp.async.wait_group 0;" ::: "memory");
    __syncthreads();

    float4 a0 = make_float4(0.f, 0.f, 0.f, 0.f);
    float4 a1 = a0;
    const __half* wrow = sWh + j * D2_STR;
#pragma unroll 4
    for (int m = 0; m < 32; ++m) {
        const uint4 wv = *(const uint4*)(wrow + (m << 3));
        const float2 w01 = __half22float2(*(const __half2*)&wv.x);
        const float2 w23 = __half22float2(*(const __half2*)&wv.y);
        const float2 w45 = __half22float2(*(const __half2*)&wv.z);
        const float2 w67 = __half22float2(*(const __half2*)&wv.w);
        const float4 f0a = *(const float4*)(&sF[rb + 0][m << 3]);
        const float4 f0b = *(const float4*)(&sF[rb + 0][(m << 3) + 4]);
        const float4 f1a = *(const float4*)(&sF[rb + 1][m << 3]);
        const float4 f1b = *(const float4*)(&sF[rb + 1][(m << 3) + 4]);
        a0.x = fmaf(f0a.x, w01.x, a0.x); a0.y = fmaf(f0a.y, w01.y, a0.y);
        a0.z = fmaf(f0a.z, w23.x, a0.z); a0.w = fmaf(f0a.w, w23.y, a0.w);
        a0.x = fmaf(f0b.x, w45.x, a0.x); a0.y = fmaf(f0b.y, w45.y, a0.y);
        a0.z = fmaf(f0b.z, w67.x, a0.z); a0.w = fmaf(f0b.w, w67.y, a0.w);
        a1.x = fmaf(f1a.x, w01.x, a1.x); a1.y = fmaf(f1a.y, w01.y, a1.y);
        a1.z = fmaf(f1a.z, w23.x, a1.z); a1.w = fmaf(f1a.w, w23.y, a1.w);
        a1.x = fmaf(f1b.x, w45.x, a1.x); a1.y = fmaf(f1b.y, w45.y, a1.y);
        a1.z = fmaf(f1b.z, w67.x, a1.z); a1.w = fmaf(f1b.w, w67.y, a1.w);
    }

    const float bj = sB1[j];
    const float w2a = sW2[j], w2b = sW2[128 + j];
    const float h0 = fmaxf((a0.x + a0.y) + (a0.z + a0.w) + bj, 0.f);
    const float h1 = fmaxf((a1.x + a1.y) + (a1.z + a1.w) + bj, 0.f);

    float p00 = h0 * w2a, p01 = h0 * w2b;
    float p10 = h1 * w2a, p11 = h1 * w2b;
#pragma unroll
    for (int off = 16; off; off >>= 1) {
        p00 += __shfl_xor_sync(0xffffffffu, p00, off);
        p01 += __shfl_xor_sync(0xffffffffu, p01, off);
        p10 += __shfl_xor_sync(0xffffffffu, p10, off);
        p11 += __shfl_xor_sync(0xffffffffu, p11, off);
    }
    if (lane == 0) {
        sP[warp][0][0] = p00; sP[warp][0][1] = p01;
        sP[warp][1][0] = p10; sP[warp][1][1] = p11;
    }
    __syncthreads();

    if (tid < 8) {
        const int r = tid;
        const int wbase = (r >> 1) << 2;
        const int lr = r & 1;
        const int row = blockIdx.x * 8 + r;
        float o0 = bb0, o1 = bb1;
#pragma unroll
        for (int w2 = 0; w2 < 4; ++w2) {
            o0 += sP[wbase + w2][lr][0];
            o1 += sP[wbase + w2][lr][1];
        }
        const float mm = fmaxf(o0, o1);
        const float z0 = expf(o0 - mm), z1 = expf(o1 - mm);
        const float inv = 1.f / (z0 + z1);
        out[row * 2]     = z0 * inv;
        out[row * 2 + 1] = z1 * inv;
    }
}

// ============================================================================
extern "C" void kernel_launch(void* const* d_in, const int* in_sizes, int n_in,
                              void* d_out, int out_size) {
    const int*   batch     = (const int*)d_in[0];
    const int*   node_type = (const int*)d_in[1];
    const int*   nbr_type  = (const int*)d_in[2];
    const int*   ext_nbr   = (const int*)d_in[3];
    const float* impact    = (const float*)d_in[4];
    const float* W         = (const float*)d_in[5];
    const float* M         = (const float*)d_in[6];
    const float* U         = (const float*)d_in[7];
    const float* V         = (const float*)d_in[8];
    const float* W1        = (const float*)d_in[9];
    const float* b1        = (const float*)d_in[10];
    const float* W2        = (const float*)d_in[11];
    const float* b2        = (const float*)d_in[12];
    float* out = (float*)d_out;

    cudaFuncSetAttribute(kA, cudaFuncAttributeMaxDynamicSharedMemorySize, SMEM_A);
    cudaFuncSetAttribute(kC, cudaFuncAttributeMaxDynamicSharedMemorySize, SMEM_C);
    cudaFuncSetAttribute(kD, cudaFuncAttributeMaxDynamicSharedMemorySize, SMEM_D);

    // diagnostic: one dummy -> ncu's -s window lands on kC (verify the fix)
    kNop<<<1, 32>>>();

    kA<<<(NTYPES + 127) / 128, 256, SMEM_A>>>(impact, W, M, W1);
    kB<<<NG, 256>>>(node_type, nbr_type);
    kC<<<NG / C_ROWS, 512, SMEM_C>>>(U, V, ext_nbr);
    kD<<<NB / 8, 512, SMEM_D>>>(batch, b1, W2, b2, out);
}